// round 2
// baseline (speedup 1.0000x reference)
#include <cuda_runtime.h>

// Problem constants
#define R_ 2
#define CH_ 2
#define NN 20000
#define EE 100000
#define CC 256
#define ED_ 16
#define RC 4                 // R_*CH_
#define MROWS (RC * NN)      // 80000 rows

// Scratch (device globals: no allocation allowed in kernel_launch)
__device__ float g_xl[(size_t)MROWS * CC];    // x @ lin_W + lin_b
__device__ float g_sums[(size_t)MROWS * CC];  // scatter sums
__device__ float g_inv[NN];                   // 1/max(cnt,1)
__device__ int   g_cnt[NN];

// ---------------------------------------------------------------------------
// zero sums (must run each replay)
__global__ void zero_sums_k() {
    size_t total = (size_t)MROWS * CC / 4;
    float4 z = make_float4(0.f, 0.f, 0.f, 0.f);
    for (size_t i = blockIdx.x * blockDim.x + threadIdx.x; i < total;
         i += (size_t)gridDim.x * blockDim.x)
        reinterpret_cast<float4*>(g_sums)[i] = z;
}

// count edges per dst  (edge_index is int32: JAX silently downcasts int64)
__global__ void count_k(const int* __restrict__ ei) {
    int e = blockIdx.x * blockDim.x + threadIdx.x;
    if (e < EE) {
        int d = ei[EE + e];
        if (d >= 0 && d < NN) atomicAdd(&g_cnt[d], 1);
    }
}

// inv = 1/max(cnt,1); reset cnt for next replay
__global__ void inv_k() {
    int n = blockIdx.x * blockDim.x + threadIdx.x;
    if (n < NN) {
        int c = g_cnt[n];
        g_inv[n] = 1.0f / fmaxf((float)c, 1.0f);
        g_cnt[n] = 0;
    }
}

// ---------------------------------------------------------------------------
// SGEMM 1: g_xl = x @ lin_W + lin_b   (M=80000, N=256, K=256)
// BM=128, BN=64, BK=16, 256 threads, thread tile 8x4
#define BM 128
#define BN 64
#define BK 16

__global__ __launch_bounds__(256) void gemm_lin_k(
    const float* __restrict__ A, const float* __restrict__ B,
    const float* __restrict__ bias) {
    __shared__ float As[BK][BM];
    __shared__ float Bs[BK][BN];
    const int bx = blockIdx.x;          // n-tile 0..3
    const int by = blockIdx.y;          // m-tile 0..624
    const int tid = threadIdx.x;
    const int tx = tid & 15;            // 0..15 (n dir)
    const int ty = tid >> 4;            // 0..15 (m dir)
    const int row0 = by * BM;
    const int col0 = bx * BN;

    float acc[8][4];
#pragma unroll
    for (int i = 0; i < 8; i++)
#pragma unroll
        for (int j = 0; j < 4; j++) acc[i][j] = 0.f;

    for (int kt = 0; kt < 256; kt += BK) {
        // A tile 128x16 -> transposed into As[k][m]
#pragma unroll
        for (int i = 0; i < 2; i++) {
            int l = tid + i * 256;           // 0..511
            int ar = l >> 2;                 // 0..127
            int ac = (l & 3) * 4;            // 0,4,8,12
            float4 v = *reinterpret_cast<const float4*>(
                &A[(size_t)(row0 + ar) * CC + kt + ac]);
            As[ac + 0][ar] = v.x; As[ac + 1][ar] = v.y;
            As[ac + 2][ar] = v.z; As[ac + 3][ar] = v.w;
        }
        // B tile 16x64
        {
            int br = tid >> 4;               // 0..15
            int bc = (tid & 15) * 4;
            *reinterpret_cast<float4*>(&Bs[br][bc]) =
                *reinterpret_cast<const float4*>(&B[(size_t)(kt + br) * CC + col0 + bc]);
        }
        __syncthreads();
#pragma unroll
        for (int k = 0; k < BK; k++) {
            float4 a0 = *reinterpret_cast<float4*>(&As[k][ty * 8]);
            float4 a1 = *reinterpret_cast<float4*>(&As[k][ty * 8 + 4]);
            float4 b0 = *reinterpret_cast<float4*>(&Bs[k][tx * 4]);
            float a[8] = {a0.x, a0.y, a0.z, a0.w, a1.x, a1.y, a1.z, a1.w};
            float b[4] = {b0.x, b0.y, b0.z, b0.w};
#pragma unroll
            for (int i = 0; i < 8; i++)
#pragma unroll
                for (int j = 0; j < 4; j++) acc[i][j] += a[i] * b[j];
        }
        __syncthreads();
    }
#pragma unroll
    for (int i = 0; i < 8; i++) {
        int m = row0 + ty * 8 + i;
#pragma unroll
        for (int j = 0; j < 4; j++) {
            int n = col0 + tx * 4 + j;
            g_xl[(size_t)m * CC + n] = acc[i][j] + bias[n];
        }
    }
}

// ---------------------------------------------------------------------------
// Message + scatter: one block per edge, 256 threads (one per channel).
// Fuses bond encoder (edge_attr @ bond_W + bond_b), gather, GELU(exact),
// edge_weight multiply, and atomic scatter-add for all 4 (r,ch) replicas.
__global__ __launch_bounds__(256) void msg_k(
    const float* __restrict__ edge_attr, const float* __restrict__ ew,
    const int* __restrict__ ei, const float* __restrict__ bond_W,
    const float* __restrict__ bond_b) {
    const int e = blockIdx.x;
    const int c = threadIdx.x;
    __shared__ float ea[ED_];
    __shared__ float w_s[RC];
    __shared__ int src_s, dst_s;
    if (c < ED_) ea[c] = edge_attr[(size_t)e * ED_ + c];
    if (c < RC)  w_s[c] = ew[(size_t)c * EE + e];
    if (c == 0) {
        int s = ei[e], d = ei[EE + e];
        src_s = (s >= 0 && s < NN) ? s : 0;
        dst_s = (d >= 0 && d < NN) ? d : 0;
    }
    __syncthreads();

    float emb = bond_b[c];
#pragma unroll
    for (int d = 0; d < ED_; d++) emb += ea[d] * bond_W[d * CC + c];

    const int src = src_s, dst = dst_s;
#pragma unroll
    for (int rc = 0; rc < RC; rc++) {
        float t = g_xl[((size_t)(rc * NN + src)) * CC + c] + emb;
        float g = 0.5f * t * (1.0f + erff(t * 0.70710678118654752f));
        atomicAdd(&g_sums[((size_t)(rc * NN + dst)) * CC + c], g * w_s[rc]);
    }
}

// ---------------------------------------------------------------------------
// Final fused GEMM: out = [sums*inv | x] @ [[linl_W],[linr_W]] + linl_b
// M=80000, N=256, virtual K=512
__global__ __launch_bounds__(256) void gemm_final_k(
    const float* __restrict__ X, const float* __restrict__ Wl,
    const float* __restrict__ Wr, const float* __restrict__ bl,
    float* __restrict__ Cout) {
    __shared__ float As[BK][BM];
    __shared__ float Bs[BK][BN];
    const int bx = blockIdx.x;
    const int by = blockIdx.y;
    const int tid = threadIdx.x;
    const int tx = tid & 15;
    const int ty = tid >> 4;
    const int row0 = by * BM;
    const int col0 = bx * BN;

    float acc[8][4];
#pragma unroll
    for (int i = 0; i < 8; i++)
#pragma unroll
        for (int j = 0; j < 4; j++) acc[i][j] = 0.f;

    for (int kt = 0; kt < 512; kt += BK) {
        const bool first = (kt < 256);
        // A tile
#pragma unroll
        for (int i = 0; i < 2; i++) {
            int l = tid + i * 256;
            int ar = l >> 2;
            int ac = (l & 3) * 4;
            int m = row0 + ar;
            float4 v;
            if (first) {
                v = *reinterpret_cast<const float4*>(
                    &g_sums[(size_t)m * CC + kt + ac]);
                float inv = g_inv[m % NN];
                v.x *= inv; v.y *= inv; v.z *= inv; v.w *= inv;
            } else {
                v = *reinterpret_cast<const float4*>(
                    &X[(size_t)m * CC + (kt - 256) + ac]);
            }
            As[ac + 0][ar] = v.x; As[ac + 1][ar] = v.y;
            As[ac + 2][ar] = v.z; As[ac + 3][ar] = v.w;
        }
        // B tile
        {
            int br = tid >> 4;
            int bc = (tid & 15) * 4;
            const float* Bsrc = first ? Wl : Wr;
            int kk = first ? (kt + br) : (kt - 256 + br);
            *reinterpret_cast<float4*>(&Bs[br][bc]) =
                *reinterpret_cast<const float4*>(&Bsrc[(size_t)kk * CC + col0 + bc]);
        }
        __syncthreads();
#pragma unroll
        for (int k = 0; k < BK; k++) {
            float4 a0 = *reinterpret_cast<float4*>(&As[k][ty * 8]);
            float4 a1 = *reinterpret_cast<float4*>(&As[k][ty * 8 + 4]);
            float4 b0 = *reinterpret_cast<float4*>(&Bs[k][tx * 4]);
            float a[8] = {a0.x, a0.y, a0.z, a0.w, a1.x, a1.y, a1.z, a1.w};
            float b[4] = {b0.x, b0.y, b0.z, b0.w};
#pragma unroll
            for (int i = 0; i < 8; i++)
#pragma unroll
                for (int j = 0; j < 4; j++) acc[i][j] += a[i] * b[j];
        }
        __syncthreads();
    }
#pragma unroll
    for (int i = 0; i < 8; i++) {
        int m = row0 + ty * 8 + i;
#pragma unroll
        for (int j = 0; j < 4; j++) {
            int n = col0 + tx * 4 + j;
            Cout[(size_t)m * CC + n] = acc[i][j] + bl[n];
        }
    }
}

// ---------------------------------------------------------------------------
extern "C" void kernel_launch(void* const* d_in, const int* in_sizes, int n_in,
                              void* d_out, int out_size) {
    const float* x         = (const float*)d_in[0];
    const float* edge_attr = (const float*)d_in[1];
    const float* edge_w    = (const float*)d_in[2];
    const float* lin_W     = (const float*)d_in[3];
    const float* lin_b     = (const float*)d_in[4];
    const float* linl_W    = (const float*)d_in[5];
    const float* linl_b    = (const float*)d_in[6];
    const float* linr_W    = (const float*)d_in[7];
    const float* bond_W    = (const float*)d_in[8];
    const float* bond_b    = (const float*)d_in[9];
    const int*   eidx      = (const int*)d_in[10];
    float* out = (float*)d_out;

    zero_sums_k<<<2048, 256>>>();
    count_k<<<(EE + 255) / 256, 256>>>(eidx);
    inv_k<<<(NN + 255) / 256, 256>>>();
    gemm_lin_k<<<dim3(CC / BN, MROWS / BM), 256>>>(x, lin_W, lin_b);
    msg_k<<<EE, 256>>>(edge_attr, edge_w, eidx, bond_W, bond_b);
    gemm_final_k<<<dim3(CC / BN, MROWS / BM), 256>>>(x, linl_W, linr_W, linl_b, out);
}

// round 10
// speedup vs baseline: 1.1245x; 1.1245x over previous
#include <cuda_runtime.h>
#include <cstdint>

#define NN 20000
#define EE 100000
#define CC 256
#define ED_ 16
#define RC 4
#define MROWS 80000

// Scratch (device globals: no allocation allowed)
__device__ float g_xl[(size_t)MROWS * CC];
__device__ float g_sums[(size_t)MROWS * CC];
__device__ float g_inv[NN];
__device__ int   g_cnt[NN];

// ---------------------------------------------------------------------------
// packed fp32x2 helpers (SASS FFMA2 — 2 fp32 FMAs per issue)
__device__ __forceinline__ unsigned long long pk2(float lo, float hi) {
    unsigned long long r;
    asm("mov.b64 %0, {%1, %2};" : "=l"(r) : "f"(lo), "f"(hi));
    return r;
}
__device__ __forceinline__ void upk2(unsigned long long v, float& lo, float& hi) {
    asm("mov.b64 {%0, %1}, %2;" : "=f"(lo), "=f"(hi) : "l"(v));
}
__device__ __forceinline__ void ffma2(unsigned long long& d, unsigned long long a,
                                      unsigned long long b) {
    asm("fma.rn.f32x2 %0, %1, %2, %0;" : "+l"(d) : "l"(a), "l"(b));
}

// ---------------------------------------------------------------------------
__global__ void sage_zero() {
    size_t total = (size_t)MROWS * CC / 4;
    float4 z = make_float4(0.f, 0.f, 0.f, 0.f);
    for (size_t i = blockIdx.x * blockDim.x + threadIdx.x; i < total;
         i += (size_t)gridDim.x * blockDim.x)
        reinterpret_cast<float4*>(g_sums)[i] = z;
}

__global__ void sage_cnt(const int* __restrict__ ei) {
    int e = blockIdx.x * blockDim.x + threadIdx.x;
    if (e < EE) {
        int d = ei[EE + e];
        if (d >= 0 && d < NN) atomicAdd(&g_cnt[d], 1);
    }
}

__global__ void sage_inv() {
    int n = blockIdx.x * blockDim.x + threadIdx.x;
    if (n < NN) {
        int c = g_cnt[n];
        g_inv[n] = 1.0f / fmaxf((float)c, 1.0f);
        g_cnt[n] = 0;
    }
}

// ---------------------------------------------------------------------------
// SGEMM 1 (f32x2 inner loop): g_xl = x @ lin_W + lin_b  (M=80000,N=256,K=256)
#define BM 128
#define BN 64
#define BK 16

__global__ __launch_bounds__(256) void sage_g1(
    const float* __restrict__ A, const float* __restrict__ B,
    const float* __restrict__ bias) {
    __shared__ float As[BK][BM];
    __shared__ float Bs[BK][BN];
    const int bx = blockIdx.x, by = blockIdx.y;
    const int tid = threadIdx.x;
    const int tx = tid & 15, ty = tid >> 4;
    const int row0 = by * BM, col0 = bx * BN;

    unsigned long long acc[8][2];
#pragma unroll
    for (int i = 0; i < 8; i++) { acc[i][0] = 0ull; acc[i][1] = 0ull; }

    for (int kt = 0; kt < 256; kt += BK) {
#pragma unroll
        for (int i = 0; i < 2; i++) {
            int l = tid + i * 256;
            int ar = l >> 2, ac = (l & 3) * 4;
            float4 v = *(const float4*)&A[(size_t)(row0 + ar) * CC + kt + ac];
            As[ac + 0][ar] = v.x; As[ac + 1][ar] = v.y;
            As[ac + 2][ar] = v.z; As[ac + 3][ar] = v.w;
        }
        {
            int br = tid >> 4, bc = (tid & 15) * 4;
            *(float4*)&Bs[br][bc] =
                *(const float4*)&B[(size_t)(kt + br) * CC + col0 + bc];
        }
        __syncthreads();
#pragma unroll
        for (int k = 0; k < BK; k++) {
            float4 a0 = *(float4*)&As[k][ty * 8];
            float4 a1 = *(float4*)&As[k][ty * 8 + 4];
            unsigned long long b01 = *(unsigned long long*)&Bs[k][tx * 4];
            unsigned long long b23 = *(unsigned long long*)&Bs[k][tx * 4 + 2];
            float a[8] = {a0.x, a0.y, a0.z, a0.w, a1.x, a1.y, a1.z, a1.w};
#pragma unroll
            for (int i = 0; i < 8; i++) {
                unsigned long long ad = pk2(a[i], a[i]);
                ffma2(acc[i][0], ad, b01);
                ffma2(acc[i][1], ad, b23);
            }
        }
        __syncthreads();
    }
#pragma unroll
    for (int i = 0; i < 8; i++) {
        int m = row0 + ty * 8 + i;
        int n = col0 + tx * 4;
        float v0, v1, v2, v3;
        upk2(acc[i][0], v0, v1);
        upk2(acc[i][1], v2, v3);
        float4 o = make_float4(v0 + bias[n], v1 + bias[n + 1],
                               v2 + bias[n + 2], v3 + bias[n + 3]);
        *(float4*)&g_xl[(size_t)m * CC + n] = o;
    }
}

// ---------------------------------------------------------------------------
// SGEMM 2 (f32x2): out = [sums*inv | x] @ [[linl_W],[linr_W]] + linl_b, K=512
__global__ __launch_bounds__(256) void sage_g2(
    const float* __restrict__ X, const float* __restrict__ Wl,
    const float* __restrict__ Wr, const float* __restrict__ bl,
    float* __restrict__ Cout) {
    __shared__ float As[BK][BM];
    __shared__ float Bs[BK][BN];
    const int bx = blockIdx.x, by = blockIdx.y;
    const int tid = threadIdx.x;
    const int tx = tid & 15, ty = tid >> 4;
    const int row0 = by * BM, col0 = bx * BN;

    unsigned long long acc[8][2];
#pragma unroll
    for (int i = 0; i < 8; i++) { acc[i][0] = 0ull; acc[i][1] = 0ull; }

    for (int kt = 0; kt < 512; kt += BK) {
        const bool first = (kt < 256);
#pragma unroll
        for (int i = 0; i < 2; i++) {
            int l = tid + i * 256;
            int ar = l >> 2, ac = (l & 3) * 4;
            int m = row0 + ar;
            float4 v;
            if (first) {
                v = *(const float4*)&g_sums[(size_t)m * CC + kt + ac];
                float inv = g_inv[m % NN];
                v.x *= inv; v.y *= inv; v.z *= inv; v.w *= inv;
            } else {
                v = *(const float4*)&X[(size_t)m * CC + (kt - 256) + ac];
            }
            As[ac + 0][ar] = v.x; As[ac + 1][ar] = v.y;
            As[ac + 2][ar] = v.z; As[ac + 3][ar] = v.w;
        }
        {
            int br = tid >> 4, bc = (tid & 15) * 4;
            const float* Bsrc = first ? Wl : Wr;
            int kk = first ? (kt + br) : (kt - 256 + br);
            *(float4*)&Bs[br][bc] =
                *(const float4*)&Bsrc[(size_t)kk * CC + col0 + bc];
        }
        __syncthreads();
#pragma unroll
        for (int k = 0; k < BK; k++) {
            float4 a0 = *(float4*)&As[k][ty * 8];
            float4 a1 = *(float4*)&As[k][ty * 8 + 4];
            unsigned long long b01 = *(unsigned long long*)&Bs[k][tx * 4];
            unsigned long long b23 = *(unsigned long long*)&Bs[k][tx * 4 + 2];
            float a[8] = {a0.x, a0.y, a0.z, a0.w, a1.x, a1.y, a1.z, a1.w};
#pragma unroll
            for (int i = 0; i < 8; i++) {
                unsigned long long ad = pk2(a[i], a[i]);
                ffma2(acc[i][0], ad, b01);
                ffma2(acc[i][1], ad, b23);
            }
        }
        __syncthreads();
    }
#pragma unroll
    for (int i = 0; i < 8; i++) {
        int m = row0 + ty * 8 + i;
        int n = col0 + tx * 4;
        float v0, v1, v2, v3;
        upk2(acc[i][0], v0, v1);
        upk2(acc[i][1], v2, v3);
        float4 o = make_float4(v0 + bl[n], v1 + bl[n + 1],
                               v2 + bl[n + 2], v3 + bl[n + 3]);
        *(float4*)&Cout[(size_t)m * CC + n] = o;
    }
}

// ---------------------------------------------------------------------------
// Message + scatter: fuses bond encoder, gather, GELU(exact), weight, atomics
__global__ __launch_bounds__(256) void sage_msg(
    const float* __restrict__ edge_attr, const float* __restrict__ ew,
    const int* __restrict__ ei, const float* __restrict__ bond_W,
    const float* __restrict__ bond_b) {
    const int e = blockIdx.x;
    const int c = threadIdx.x;
    __shared__ float ea[ED_];
    __shared__ float w_s[RC];
    __shared__ int src_s, dst_s;
    if (c < ED_) ea[c] = edge_attr[(size_t)e * ED_ + c];
    if (c < RC)  w_s[c] = ew[(size_t)c * EE + e];
    if (c == 0) {
        int s = ei[e], d = ei[EE + e];
        src_s = (s >= 0 && s < NN) ? s : 0;
        dst_s = (d >= 0 && d < NN) ? d : 0;
    }
    __syncthreads();

    float emb = bond_b[c];
#pragma unroll
    for (int d = 0; d < ED_; d++) emb += ea[d] * bond_W[d * CC + c];

    const int src = src_s, dst = dst_s;
#pragma unroll
    for (int rc = 0; rc < RC; rc++) {
        float t = g_xl[((size_t)(rc * NN + src)) * CC + c] + emb;
        float g = 0.5f * t * (1.0f + erff(t * 0.70710678118654752f));
        atomicAdd(&g_sums[((size_t)(rc * NN + dst)) * CC + c], g * w_s[rc]);
    }
}

// ---------------------------------------------------------------------------
extern "C" void kernel_launch(void* const* d_in, const int* in_sizes, int n_in,
                              void* d_out, int out_size) {
    const float* x         = (const float*)d_in[0];
    const float* edge_attr = (const float*)d_in[1];
    const float* edge_w    = (const float*)d_in[2];
    const float* lin_W     = (const float*)d_in[3];
    const float* lin_b     = (const float*)d_in[4];
    const float* linl_W    = (const float*)d_in[5];
    const float* linl_b    = (const float*)d_in[6];
    const float* linr_W    = (const float*)d_in[7];
    const float* bond_W    = (const float*)d_in[8];
    const float* bond_b    = (const float*)d_in[9];
    const int*   eidx      = (const int*)d_in[10];
    float* out = (float*)d_out;

    sage_zero<<<2048, 256>>>();
    sage_cnt<<<(EE + 255) / 256, 256>>>(eidx);
    sage_inv<<<(NN + 255) / 256, 256>>>();
    sage_g1<<<dim3(CC / BN, MROWS / BM), 256>>>(x, lin_W, lin_b);
    sage_msg<<<EE, 256>>>(edge_attr, edge_w, eidx, bond_W, bond_b);
    sage_g2<<<dim3(CC / BN, MROWS / BM), 256>>>(x, linl_W, linr_W, linl_b, out);
}